// round 4
// baseline (speedup 1.0000x reference)
#include <cuda_runtime.h>

// ---------------------------------------------------------------------------
// MID_LOSS: B=8192, E=512, M=8 (features), C=14 (classes), BETA=0.3
// inputs (metadata order): x [B, E*M] f32, y [B, C] i32, wordvec [1, E, C] f32
// output: scalar f32 (mean loss)
// ---------------------------------------------------------------------------

#define FULLMASK 0xFFFFFFFFu

static __device__ float g_gram[14 * 14];      // Gram = w^T w  [C, C]
static __device__ float g_partials[1024];     // per-block loss sums

__device__ __forceinline__ unsigned long long ffma2(unsigned long long a,
                                                    unsigned long long b,
                                                    unsigned long long c) {
    unsigned long long d;
    asm("fma.rn.f32x2 %0, %1, %2, %3;" : "=l"(d) : "l"(a), "l"(b), "l"(c));
    return d;
}

__device__ __forceinline__ float softplus_f(float v) {
    // numerically stable log1p(exp(v))
    return fmaxf(v, 0.0f) + log1pf(expf(-fabsf(v)));
}

// ---------------------------------------------------------------------------
// Kernel 1: Gram[c, c2] = sum_e w[e, c] * w[e, c2]   (196 blocks x 128 thr)
// ---------------------------------------------------------------------------
__global__ void gram_kernel(const float* __restrict__ w) {
    const int c  = blockIdx.x / 14;
    const int c2 = blockIdx.x % 14;
    const int tid = threadIdx.x;

    float s = 0.0f;
    #pragma unroll 4
    for (int e = tid; e < 512; e += 128)
        s += w[e * 14 + c] * w[e * 14 + c2];

    #pragma unroll
    for (int o = 16; o; o >>= 1) s += __shfl_xor_sync(FULLMASK, s, o);

    __shared__ float red[4];
    if ((tid & 31) == 0) red[tid >> 5] = s;
    __syncthreads();
    if (tid == 0) g_gram[blockIdx.x] = red[0] + red[1] + red[2] + red[3];
}

// ---------------------------------------------------------------------------
// Kernel 2: main per-sample loss. 1024 blocks x 128 threads, 8 samples/block.
//  - w staged transposed in smem [c][e]
//  - x row staged transposed in smem [m][e] (stride 516 -> conflict-free)
//  - 4 warps/sample, each warp computes a 4m x 7c tile of dot[m][c] with
//    packed f32x2 FMAs, e split across lanes (e ≡ 2*lane mod 64)
//  - epilogue (warp 0): max over m, ranking pair sum, Gram-based diversity
// ---------------------------------------------------------------------------
__global__ __launch_bounds__(128) void main_kernel(const float* __restrict__ x,
                                                   const int*   __restrict__ y,
                                                   const float* __restrict__ w) {
    __shared__ __align__(16) float w_s[14 * 512];   // [c][e]
    __shared__ __align__(16) float un_s[8 * 516];   // [m][e], padded stride 516
    __shared__ float dot_s[112];                    // [m][c]
    __shared__ float dotc_s[16];
    __shared__ float l1part[4];

    const int tid  = threadIdx.x;
    const int lane = tid & 31;
    const int wid  = tid >> 5;

    // stage w transposed: coalesced read, scattered smem store (one-time)
    for (int i = tid; i < 512 * 14; i += 128) {
        int e = i / 14, c = i - e * 14;
        w_s[c * 512 + e] = w[i];
    }

    const int mg = (wid >> 1) * 4;   // m tile base: 0 or 4
    const int cg = (wid & 1) * 7;    // c tile base: 0 or 7

    float block_sum = 0.0f;

    for (int s = 0; s < 8; ++s) {
        const int b = blockIdx.x * 8 + s;
        __syncthreads();   // w_s ready (iter 0) / un_s,dot_s reuse safe (iter>0)

        // ---- load x row, transpose into un_s[m][e] ----
        const float4* xr = (const float4*)(x + (size_t)b * 4096);
        #pragma unroll
        for (int k = 0; k < 8; ++k) {
            float4 v = xr[tid + 128 * k];
            int j = (tid + 128 * k) * 4;
            un_s[((j    ) & 7) * 516 + ((j    ) >> 3)] = v.x;
            un_s[((j + 1) & 7) * 516 + ((j + 1) >> 3)] = v.y;
            un_s[((j + 2) & 7) * 516 + ((j + 2) >> 3)] = v.z;
            un_s[((j + 3) & 7) * 516 + ((j + 3) >> 3)] = v.w;
        }
        __syncthreads();

        // ---- l1_err: unbiased variance over m per e, L1 over e ----
        {
            float l1 = 0.0f;
            #pragma unroll
            for (int k = 0; k < 4; ++k) {
                int e = tid + 128 * k;
                float s1 = 0.0f, s2 = 0.0f;
                #pragma unroll
                for (int m = 0; m < 8; ++m) {
                    float v = un_s[m * 516 + e];
                    s1 += v;
                    s2 += v * v;
                }
                float var = (s2 - s1 * s1 * 0.125f) * (1.0f / 7.0f);
                l1 += fabsf(var);
            }
            #pragma unroll
            for (int o = 16; o; o >>= 1) l1 += __shfl_xor_sync(FULLMASK, l1, o);
            if (lane == 0) l1part[wid] = l1;
        }

        // ---- GEMM tile: dot[mg..mg+3][cg..cg+6], packed f32x2 over e ----
        unsigned long long acc[4][7];
        #pragma unroll
        for (int mi = 0; mi < 4; ++mi)
            #pragma unroll
            for (int ci = 0; ci < 7; ++ci) acc[mi][ci] = 0ull;

        #pragma unroll
        for (int i = 0; i < 8; ++i) {
            const int p2 = (lane + 32 * i) * 2;   // even e index
            unsigned long long a2[4], b2[7];
            #pragma unroll
            for (int mi = 0; mi < 4; ++mi)
                a2[mi] = *(const unsigned long long*)(un_s + (mg + mi) * 516 + p2);
            #pragma unroll
            for (int ci = 0; ci < 7; ++ci)
                b2[ci] = *(const unsigned long long*)(w_s + (cg + ci) * 512 + p2);
            #pragma unroll
            for (int mi = 0; mi < 4; ++mi)
                #pragma unroll
                for (int ci = 0; ci < 7; ++ci)
                    acc[mi][ci] = ffma2(a2[mi], b2[ci], acc[mi][ci]);
        }

        // ---- reduce accumulators across lanes, write dot_s ----
        #pragma unroll
        for (int mi = 0; mi < 4; ++mi) {
            #pragma unroll
            for (int ci = 0; ci < 7; ++ci) {
                float2 f = *(float2*)&acc[mi][ci];
                float v = f.x + f.y;
                #pragma unroll
                for (int o = 16; o; o >>= 1) v += __shfl_xor_sync(FULLMASK, v, o);
                if (lane == 0) dot_s[(mg + mi) * 14 + (cg + ci)] = v;
            }
        }
        __syncthreads();

        // ---- epilogue: warp 0 only ----
        if (wid == 0) {
            const bool inc = lane < 14;
            float dmax = -3.402823466e38f;
            if (inc) {
                dmax = dot_s[lane];
                #pragma unroll
                for (int m = 1; m < 8; ++m) dmax = fmaxf(dmax, dot_s[m * 14 + lane]);
                dotc_s[lane] = dmax;
            }
            int yv = inc ? y[b * 14 + lane] : 0;
            unsigned pm = __ballot_sync(FULLMASK, inc && (yv == 1));
            unsigned nm = (~pm) & 0x3FFFu;
            const int npos = __popc(pm);
            const int nneg = __popc(nm);
            __syncwarp();

            float sloc = 0.0f, diag = 0.0f, row = 0.0f;
            const bool isp = inc && ((pm >> lane) & 1);
            if (isp) {
                const float dp = dmax;
                if (nneg > 0) {
                    #pragma unroll
                    for (int n = 0; n < 14; ++n)
                        if ((nm >> n) & 1) sloc += softplus_f(dotc_s[n] - dp);
                } else {
                    sloc = softplus_f(-dp);
                }
                diag = g_gram[lane * 14 + lane];
                #pragma unroll
                for (int c2 = 0; c2 < 14; ++c2)
                    if ((pm >> c2) & 1) row += g_gram[lane * 14 + c2];
            }
            #pragma unroll
            for (int o = 16; o; o >>= 1) {
                sloc += __shfl_xor_sync(FULLMASK, sloc, o);
                diag += __shfl_xor_sync(FULLMASK, diag, o);
                row  += __shfl_xor_sync(FULLMASK, row,  o);
            }
            if (lane == 0) {
                const float npf = (float)npos;
                float tv = 0.0f;
                if (npos > 1) tv = (diag - row / npf) / (npf - 1.0f);
                const float base = sloc / npf;
                const float l1t = l1part[0] + l1part[1] + l1part[2] + l1part[3];
                const float loss = 2.0f * (0.7f * (1.0f + tv) * base + 0.3f * l1t);
                block_sum += loss;
            }
        }
    }

    if (tid == 0) g_partials[blockIdx.x] = block_sum;
}

// ---------------------------------------------------------------------------
// Kernel 3: deterministic final reduction of 1024 partials -> mean
// ---------------------------------------------------------------------------
__global__ void reduce_kernel(float* __restrict__ out) {
    const int tid = threadIdx.x;   // 1024 threads
    float v = g_partials[tid];
    #pragma unroll
    for (int o = 16; o; o >>= 1) v += __shfl_xor_sync(FULLMASK, v, o);
    __shared__ float red[32];
    if ((tid & 31) == 0) red[tid >> 5] = v;
    __syncthreads();
    if (tid < 32) {
        float s = red[tid];
        #pragma unroll
        for (int o = 16; o; o >>= 1) s += __shfl_xor_sync(FULLMASK, s, o);
        if (tid == 0) out[0] = s * (1.0f / 8192.0f);
    }
}

extern "C" void kernel_launch(void* const* d_in, const int* in_sizes, int n_in,
                              void* d_out, int out_size) {
    const float* x = (const float*)d_in[0];
    const int*   y = (const int*)d_in[1];
    const float* w = (const float*)d_in[2];

    gram_kernel<<<196, 128>>>(w);
    main_kernel<<<1024, 128>>>(x, y, w);
    reduce_kernel<<<1, 1024>>>((float*)d_out);
}